// round 2
// baseline (speedup 1.0000x reference)
#include <cuda_runtime.h>

// ParallelBellowsLayers: per-channel 1->16->1 MLP with ReLU, C=40000, B=128, E=16.
// out[b,c] = relu( sum_e relu(x[b,c]*w1[c,e]+b1[c,e]) * w2[c,e] + b2[c] )
// Output (B,2,20000) is layout-identical to (B,C) row-major -> elementwise in x.
//
// When b1[c,:]==0 (true for this dataset):
//   sum_e relu(x*w1e)*w2e == x * (x>0 ? s_pos : s_neg)
// Precompute per channel {s_pos, s_neg, b2, flag} once per launch; the main
// pass streams x -> out with params amortized over R=8 batch rows per thread.
// Channels with nonzero b1 get flag=NaN and take an exact fallback (never
// taken on this dataset).

#define NGENES 20000
#define NTECH  2
#define CC     (NGENES * NTECH)   // 40000
#define BB     128
#define EE     16
#define RROWS  8                  // batch rows per thread in apply

// per-channel packed params: {s_pos, s_neg, bias(b2), flag(0 or NaN)}
__device__ float4 g_params[CC];

__global__ void __launch_bounds__(256)
precompute_kernel(const float* __restrict__ w1,
                  const float* __restrict__ b1,
                  const float* __restrict__ w2,
                  const float* __restrict__ b2)
{
    int c = blockIdx.x * 256 + threadIdx.x;
    if (c >= CC) return;

    const float4* w1v = reinterpret_cast<const float4*>(w1 + (size_t)c * EE);
    const float4* b1v = reinterpret_cast<const float4*>(b1 + (size_t)c * EE);
    const float4* w2v = reinterpret_cast<const float4*>(w2 + (size_t)c * EE);

    float sp = 0.f, sn = 0.f;
    bool b1zero = true;

#pragma unroll
    for (int i = 0; i < 4; ++i) {
        float4 a = w1v[i];
        float4 z = b1v[i];
        float4 w = w2v[i];
        b1zero = b1zero && (z.x == 0.f) && (z.y == 0.f) && (z.z == 0.f) && (z.w == 0.f);

        float p;
        p = a.x * w.x; sp += (a.x > 0.f) ? p : 0.f; sn += (a.x < 0.f) ? p : 0.f;
        p = a.y * w.y; sp += (a.y > 0.f) ? p : 0.f; sn += (a.y < 0.f) ? p : 0.f;
        p = a.z * w.z; sp += (a.z > 0.f) ? p : 0.f; sn += (a.z < 0.f) ? p : 0.f;
        p = a.w * w.w; sp += (a.w > 0.f) ? p : 0.f; sn += (a.w < 0.f) ? p : 0.f;
    }

    float flag = b1zero ? 0.f : __int_as_float(0x7fc00000);  // NaN => fallback
    g_params[c] = make_float4(sp, sn, b2[c], flag);
}

// Exact per-element path for channels with nonzero b1 (never taken here).
__device__ __noinline__ float bellows_exact(float xv, int c,
                                            const float* __restrict__ w1,
                                            const float* __restrict__ b1,
                                            const float* __restrict__ w2,
                                            float bias)
{
    float acc = 0.f;
    const float* w1r = w1 + (size_t)c * EE;
    const float* b1r = b1 + (size_t)c * EE;
    const float* w2r = w2 + (size_t)c * EE;
#pragma unroll 4
    for (int e = 0; e < EE; ++e) {
        float h = fmaxf(fmaf(xv, w1r[e], b1r[e]), 0.f);
        acc = fmaf(h, w2r[e], acc);
    }
    return fmaxf(acc + bias, 0.f);
}

__device__ __forceinline__ float bellows_fast(float xv, const float4& p)
{
    float s = (xv > 0.f) ? p.x : p.y;
    return fmaxf(fmaf(xv, s, p.z), 0.f);
}

__global__ void __launch_bounds__(256)
apply_kernel(const float* __restrict__ x,
             const float* __restrict__ w1,
             const float* __restrict__ b1,
             const float* __restrict__ w2,
             float* __restrict__ out)
{
    int g = blockIdx.x * 256 + threadIdx.x;   // group of 4 channels
    if (g >= CC / 4) return;
    int c  = g * 4;
    int b0 = blockIdx.y * RROWS;

    // 4 channels worth of packed params (64B, amortized over RROWS rows)
    float4 p0 = g_params[c + 0];
    float4 p1 = g_params[c + 1];
    float4 p2 = g_params[c + 2];
    float4 p3 = g_params[c + 3];

    bool any_fb = (p0.w != p0.w) || (p1.w != p1.w) || (p2.w != p2.w) || (p3.w != p3.w);

    // Batch all x loads first: 8 independent LDG.128 in flight per thread.
    float4 xv[RROWS];
#pragma unroll
    for (int r = 0; r < RROWS; ++r)
        xv[r] = *reinterpret_cast<const float4*>(x + (size_t)(b0 + r) * CC + c);

    if (!any_fb) {
#pragma unroll
        for (int r = 0; r < RROWS; ++r) {
            float4 o;
            o.x = bellows_fast(xv[r].x, p0);
            o.y = bellows_fast(xv[r].y, p1);
            o.z = bellows_fast(xv[r].z, p2);
            o.w = bellows_fast(xv[r].w, p3);
            *reinterpret_cast<float4*>(out + (size_t)(b0 + r) * CC + c) = o;
        }
    } else {
#pragma unroll
        for (int r = 0; r < RROWS; ++r) {
            float4 o;
            o.x = (p0.w != p0.w) ? bellows_exact(xv[r].x, c + 0, w1, b1, w2, p0.z)
                                 : bellows_fast(xv[r].x, p0);
            o.y = (p1.w != p1.w) ? bellows_exact(xv[r].y, c + 1, w1, b1, w2, p1.z)
                                 : bellows_fast(xv[r].y, p1);
            o.z = (p2.w != p2.w) ? bellows_exact(xv[r].z, c + 2, w1, b1, w2, p2.z)
                                 : bellows_fast(xv[r].z, p2);
            o.w = (p3.w != p3.w) ? bellows_exact(xv[r].w, c + 3, w1, b1, w2, p3.z)
                                 : bellows_fast(xv[r].w, p3);
            *reinterpret_cast<float4*>(out + (size_t)(b0 + r) * CC + c) = o;
        }
    }
}

extern "C" void kernel_launch(void* const* d_in, const int* in_sizes, int n_in,
                              void* d_out, int out_size)
{
    const float* x  = (const float*)d_in[0];   // (128, 40000)
    const float* w1 = (const float*)d_in[1];   // (40000, 16)
    const float* b1 = (const float*)d_in[2];   // (40000, 16)
    const float* w2 = (const float*)d_in[3];   // (40000, 16)
    const float* b2 = (const float*)d_in[4];   // (40000,)
    float* out = (float*)d_out;                // (128, 2, 20000) == (128, 40000)

    precompute_kernel<<<(CC + 255) / 256, 256>>>(w1, b1, w2, b2);

    dim3 grid((CC / 4 + 255) / 256, BB / RROWS);   // (40, 16)
    apply_kernel<<<grid, 256>>>(x, w1, b1, w2, out);
}

// round 3
// speedup vs baseline: 1.3753x; 1.3753x over previous
#include <cuda_runtime.h>

// ParallelBellowsLayers: per-channel 1->16->1 MLP with ReLU, C=40000, B=128, E=16.
// out[b,c] = relu( sum_e relu(x[b,c]*w1[c,e]+b1[c,e]) * w2[c,e] + b2[c] )
// Output (B,2,20000) is layout-identical to (B,C) row-major -> elementwise in x.
//
// When b1[c,:]==0 (true for this dataset):
//   sum_e relu(x*w1e)*w2e == x * (x>0 ? s_pos : s_neg)
// Precompute per channel s_pos/s_neg/b2 (SoA) once per launch; main pass
// streams x -> out, params amortized over R=4 batch rows per thread with a
// software-pipelined row loop (keeps regs low -> high occupancy; R2's batched
// version hit 80 regs / 27% occ and regressed).
// Fallback channels (nonzero b1, or non-finite s) are flagged with NaN in
// s_pos and take an exact per-element path (never taken on this dataset).

#define NGENES 20000
#define NTECH  2
#define CC     (NGENES * NTECH)   // 40000
#define BB     128
#define EE     16
#define RROWS  4                  // batch rows per thread in apply

// SoA per-channel params (NaN in g_sp[c] => exact-fallback channel)
__device__ float g_sp[CC];
__device__ float g_sn[CC];
__device__ float g_bf[CC];

__global__ void __launch_bounds__(256)
precompute_kernel(const float* __restrict__ w1,
                  const float* __restrict__ b1,
                  const float* __restrict__ w2,
                  const float* __restrict__ b2)
{
    int c = blockIdx.x * 256 + threadIdx.x;
    if (c >= CC) return;

    const float4* w1v = reinterpret_cast<const float4*>(w1 + (size_t)c * EE);
    const float4* b1v = reinterpret_cast<const float4*>(b1 + (size_t)c * EE);
    const float4* w2v = reinterpret_cast<const float4*>(w2 + (size_t)c * EE);

    float sp = 0.f, sn = 0.f;
    bool ok = true;

#pragma unroll
    for (int i = 0; i < 4; ++i) {
        float4 a = w1v[i];
        float4 z = b1v[i];
        float4 w = w2v[i];
        ok = ok && (z.x == 0.f) && (z.y == 0.f) && (z.z == 0.f) && (z.w == 0.f);

        float p;
        p = a.x * w.x; sp += (a.x > 0.f) ? p : 0.f; sn += (a.x < 0.f) ? p : 0.f;
        p = a.y * w.y; sp += (a.y > 0.f) ? p : 0.f; sn += (a.y < 0.f) ? p : 0.f;
        p = a.z * w.z; sp += (a.z > 0.f) ? p : 0.f; sn += (a.z < 0.f) ? p : 0.f;
        p = a.w * w.w; sp += (a.w > 0.f) ? p : 0.f; sn += (a.w < 0.f) ? p : 0.f;
    }

    // NaN sentinel also guards overflow in sp/sn so the fast path stays exact.
    ok = ok && isfinite(sp) && isfinite(sn);
    g_sp[c] = ok ? sp : __int_as_float(0x7fc00000);
    g_sn[c] = sn;
    g_bf[c] = b2[c];
}

// Exact per-element path for flagged channels (never taken on this dataset).
__device__ __noinline__ float bellows_exact(float xv, int c,
                                            const float* __restrict__ w1,
                                            const float* __restrict__ b1,
                                            const float* __restrict__ w2,
                                            float bias)
{
    float acc = 0.f;
    const float* w1r = w1 + (size_t)c * EE;
    const float* b1r = b1 + (size_t)c * EE;
    const float* w2r = w2 + (size_t)c * EE;
#pragma unroll 4
    for (int e = 0; e < EE; ++e) {
        float h = fmaxf(fmaf(xv, w1r[e], b1r[e]), 0.f);
        acc = fmaf(h, w2r[e], acc);
    }
    return fmaxf(acc + bias, 0.f);
}

__device__ __forceinline__ float bellows_fast(float xv, float sp, float sn, float bias)
{
    float s = (xv > 0.f) ? sp : sn;
    return fmaxf(fmaf(xv, s, bias), 0.f);
}

__global__ void __launch_bounds__(256)
apply_kernel(const float* __restrict__ x,
             const float* __restrict__ w1,
             const float* __restrict__ b1,
             const float* __restrict__ w2,
             float* __restrict__ out)
{
    int g = blockIdx.x * 256 + threadIdx.x;   // group of 4 channels
    if (g >= CC / 4) return;
    int c  = g * 4;
    int b0 = blockIdx.y * RROWS;

    // 3 param loads per thread (SoA), amortized over RROWS rows.
    float4 sp = reinterpret_cast<const float4*>(g_sp)[g];
    float4 sn = reinterpret_cast<const float4*>(g_sn)[g];
    float4 bf = reinterpret_cast<const float4*>(g_bf)[g];

    bool any_fb = (sp.x != sp.x) || (sp.y != sp.y) || (sp.z != sp.z) || (sp.w != sp.w);

    const float* xp = x + (size_t)b0 * CC + c;
    float*       op = out + (size_t)b0 * CC + c;

    if (!any_fb) {
        // Software pipeline: load row r+1 while computing/storing row r.
        float4 xa = *reinterpret_cast<const float4*>(xp);
#pragma unroll
        for (int r = 0; r < RROWS; ++r) {
            float4 xb;
            if (r + 1 < RROWS)
                xb = *reinterpret_cast<const float4*>(xp + (size_t)(r + 1) * CC);
            float4 o;
            o.x = bellows_fast(xa.x, sp.x, sn.x, bf.x);
            o.y = bellows_fast(xa.y, sp.y, sn.y, bf.y);
            o.z = bellows_fast(xa.z, sp.z, sn.z, bf.z);
            o.w = bellows_fast(xa.w, sp.w, sn.w, bf.w);
            *reinterpret_cast<float4*>(op + (size_t)r * CC) = o;
            xa = xb;
        }
    } else {
#pragma unroll
        for (int r = 0; r < RROWS; ++r) {
            float4 xv = *reinterpret_cast<const float4*>(xp + (size_t)r * CC);
            float4 o;
            o.x = (sp.x != sp.x) ? bellows_exact(xv.x, c + 0, w1, b1, w2, bf.x)
                                 : bellows_fast(xv.x, sp.x, sn.x, bf.x);
            o.y = (sp.y != sp.y) ? bellows_exact(xv.y, c + 1, w1, b1, w2, bf.y)
                                 : bellows_fast(xv.y, sp.y, sn.y, bf.y);
            o.z = (sp.z != sp.z) ? bellows_exact(xv.z, c + 2, w1, b1, w2, bf.z)
                                 : bellows_fast(xv.z, sp.z, sn.z, bf.z);
            o.w = (sp.w != sp.w) ? bellows_exact(xv.w, c + 3, w1, b1, w2, bf.w)
                                 : bellows_fast(xv.w, sp.w, sn.w, bf.w);
            *reinterpret_cast<float4*>(op + (size_t)r * CC) = o;
        }
    }
}

extern "C" void kernel_launch(void* const* d_in, const int* in_sizes, int n_in,
                              void* d_out, int out_size)
{
    const float* x  = (const float*)d_in[0];   // (128, 40000)
    const float* w1 = (const float*)d_in[1];   // (40000, 16)
    const float* b1 = (const float*)d_in[2];   // (40000, 16)
    const float* w2 = (const float*)d_in[3];   // (40000, 16)
    const float* b2 = (const float*)d_in[4];   // (40000,)
    float* out = (float*)d_out;                // (128, 2, 20000) == (128, 40000)

    precompute_kernel<<<(CC + 255) / 256, 256>>>(w1, b1, w2, b2);

    dim3 grid((CC / 4 + 255) / 256, BB / RROWS);   // (40, 32) = 1280 blocks
    apply_kernel<<<grid, 256>>>(x, w1, b1, w2, out);
}

// round 4
// speedup vs baseline: 1.4116x; 1.0264x over previous
#include <cuda_runtime.h>

// ParallelBellowsLayers: per-channel 1->16->1 MLP with ReLU, C=40000, B=128, E=16.
// out[b,c] = relu( sum_e relu(x[b,c]*w1[c,e]+b1[c,e]) * w2[c,e] + b2[c] )
// Output (B,2,20000) is layout-identical to (B,C) row-major -> elementwise in x.
//
// When b1[c,:]==0 (true for this dataset):
//   sum_e relu(x*w1e)*w2e == x * (x>0 ? s_pos : s_neg)
// Precompute per channel s_pos/s_neg/b2 (SoA, 4 threads/channel + shfl reduce),
// then apply streams x -> out with ALL 7 loads per thread issued up-front
// (3 param float4 + 4 row float4) to maximize memory-level parallelism --
// R3 showed the kernel is latency-bound with nothing saturated.
// Channels with nonzero b1 (or non-finite s) are NaN-flagged in s_pos and take
// an exact per-element path (never taken on this dataset).

#define NGENES 20000
#define NTECH  2
#define CC     (NGENES * NTECH)   // 40000
#define BB     128
#define EE     16
#define RROWS  4                  // batch rows per thread in apply

// SoA per-channel params (NaN in g_sp[c] => exact-fallback channel)
__device__ float g_sp[CC];
__device__ float g_sn[CC];
__device__ float g_bf[CC];

// 4 threads per channel: thread quad (c, part=0..3), each handles one float4
// slice of the E=16 weights, then reduces sp/sn over the quad via shfl.
__global__ void __launch_bounds__(256)
precompute_kernel(const float* __restrict__ w1,
                  const float* __restrict__ b1,
                  const float* __restrict__ w2,
                  const float* __restrict__ b2)
{
    int t = blockIdx.x * 256 + threadIdx.x;
    int c = t >> 2;
    int part = t & 3;
    if (c >= CC) return;

    size_t vi = (size_t)c * 4 + part;   // float4 index into (C, 16) arrays
    float4 a = reinterpret_cast<const float4*>(w1)[vi];
    float4 z = reinterpret_cast<const float4*>(b1)[vi];
    float4 w = reinterpret_cast<const float4*>(w2)[vi];

    bool ok = (z.x == 0.f) && (z.y == 0.f) && (z.z == 0.f) && (z.w == 0.f);

    float sp = 0.f, sn = 0.f, p;
    p = a.x * w.x; sp += (a.x > 0.f) ? p : 0.f; sn += (a.x < 0.f) ? p : 0.f;
    p = a.y * w.y; sp += (a.y > 0.f) ? p : 0.f; sn += (a.y < 0.f) ? p : 0.f;
    p = a.z * w.z; sp += (a.z > 0.f) ? p : 0.f; sn += (a.z < 0.f) ? p : 0.f;
    p = a.w * w.w; sp += (a.w > 0.f) ? p : 0.f; sn += (a.w < 0.f) ? p : 0.f;

    // poison with NaN if this slice saw nonzero b1; NaN survives the reduction
    if (!ok) sp = __int_as_float(0x7fc00000);

    sp += __shfl_xor_sync(0xffffffffu, sp, 1);
    sp += __shfl_xor_sync(0xffffffffu, sp, 2);
    sn += __shfl_xor_sync(0xffffffffu, sn, 1);
    sn += __shfl_xor_sync(0xffffffffu, sn, 2);

    if (part == 0) {
        // inf from overflow must also route to the exact fallback
        if (!isfinite(sp) || !isfinite(sn)) sp = __int_as_float(0x7fc00000);
        g_sp[c] = sp;
        g_sn[c] = sn;
        g_bf[c] = b2[c];
    }
}

// Exact per-element path for flagged channels (never taken on this dataset).
__device__ __noinline__ float bellows_exact(float xv, int c,
                                            const float* __restrict__ w1,
                                            const float* __restrict__ b1,
                                            const float* __restrict__ w2,
                                            float bias)
{
    float acc = 0.f;
    const float* w1r = w1 + (size_t)c * EE;
    const float* b1r = b1 + (size_t)c * EE;
    const float* w2r = w2 + (size_t)c * EE;
#pragma unroll 4
    for (int e = 0; e < EE; ++e) {
        float h = fmaxf(fmaf(xv, w1r[e], b1r[e]), 0.f);
        acc = fmaf(h, w2r[e], acc);
    }
    return fmaxf(acc + bias, 0.f);
}

__device__ __forceinline__ float bellows_fast(float xv, float sp, float sn, float bias)
{
    float s = (xv > 0.f) ? sp : sn;
    return fmaxf(fmaf(xv, s, bias), 0.f);
}

__global__ void __launch_bounds__(256)
apply_kernel(const float* __restrict__ x,
             const float* __restrict__ w1,
             const float* __restrict__ b1,
             const float* __restrict__ w2,
             float* __restrict__ out)
{
    int g = blockIdx.x * 256 + threadIdx.x;   // group of 4 channels
    if (g >= CC / 4) return;
    int c  = g * 4;
    int b0 = blockIdx.y * RROWS;

    const float* xp = x + (size_t)b0 * CC + c;
    float*       op = out + (size_t)b0 * CC + c;

    // Issue ALL loads up-front: 3 param vectors + 4 row vectors = 7 LDG.128
    // in flight per thread (latency-bound kernel; maximize MLP).
    float4 sp = reinterpret_cast<const float4*>(g_sp)[g];
    float4 sn = reinterpret_cast<const float4*>(g_sn)[g];
    float4 bf = reinterpret_cast<const float4*>(g_bf)[g];

    float4 xv0 = *reinterpret_cast<const float4*>(xp);
    float4 xv1 = *reinterpret_cast<const float4*>(xp + (size_t)1 * CC);
    float4 xv2 = *reinterpret_cast<const float4*>(xp + (size_t)2 * CC);
    float4 xv3 = *reinterpret_cast<const float4*>(xp + (size_t)3 * CC);

    bool any_fb = (sp.x != sp.x) || (sp.y != sp.y) || (sp.z != sp.z) || (sp.w != sp.w);

    if (!any_fb) {
        float4 o;
        o.x = bellows_fast(xv0.x, sp.x, sn.x, bf.x);
        o.y = bellows_fast(xv0.y, sp.y, sn.y, bf.y);
        o.z = bellows_fast(xv0.z, sp.z, sn.z, bf.z);
        o.w = bellows_fast(xv0.w, sp.w, sn.w, bf.w);
        *reinterpret_cast<float4*>(op) = o;
        o.x = bellows_fast(xv1.x, sp.x, sn.x, bf.x);
        o.y = bellows_fast(xv1.y, sp.y, sn.y, bf.y);
        o.z = bellows_fast(xv1.z, sp.z, sn.z, bf.z);
        o.w = bellows_fast(xv1.w, sp.w, sn.w, bf.w);
        *reinterpret_cast<float4*>(op + (size_t)1 * CC) = o;
        o.x = bellows_fast(xv2.x, sp.x, sn.x, bf.x);
        o.y = bellows_fast(xv2.y, sp.y, sn.y, bf.y);
        o.z = bellows_fast(xv2.z, sp.z, sn.z, bf.z);
        o.w = bellows_fast(xv2.w, sp.w, sn.w, bf.w);
        *reinterpret_cast<float4*>(op + (size_t)2 * CC) = o;
        o.x = bellows_fast(xv3.x, sp.x, sn.x, bf.x);
        o.y = bellows_fast(xv3.y, sp.y, sn.y, bf.y);
        o.z = bellows_fast(xv3.z, sp.z, sn.z, bf.z);
        o.w = bellows_fast(xv3.w, sp.w, sn.w, bf.w);
        *reinterpret_cast<float4*>(op + (size_t)3 * CC) = o;
    } else {
        float4 xs[RROWS] = {xv0, xv1, xv2, xv3};
#pragma unroll
        for (int r = 0; r < RROWS; ++r) {
            float4 xv = xs[r];
            float4 o;
            o.x = (sp.x != sp.x) ? bellows_exact(xv.x, c + 0, w1, b1, w2, bf.x)
                                 : bellows_fast(xv.x, sp.x, sn.x, bf.x);
            o.y = (sp.y != sp.y) ? bellows_exact(xv.y, c + 1, w1, b1, w2, bf.y)
                                 : bellows_fast(xv.y, sp.y, sn.y, bf.y);
            o.z = (sp.z != sp.z) ? bellows_exact(xv.z, c + 2, w1, b1, w2, bf.z)
                                 : bellows_fast(xv.z, sp.z, sn.z, bf.z);
            o.w = (sp.w != sp.w) ? bellows_exact(xv.w, c + 3, w1, b1, w2, bf.w)
                                 : bellows_fast(xv.w, sp.w, sn.w, bf.w);
            *reinterpret_cast<float4*>(op + (size_t)r * CC) = o;
        }
    }
}

extern "C" void kernel_launch(void* const* d_in, const int* in_sizes, int n_in,
                              void* d_out, int out_size)
{
    const float* x  = (const float*)d_in[0];   // (128, 40000)
    const float* w1 = (const float*)d_in[1];   // (40000, 16)
    const float* b1 = (const float*)d_in[2];   // (40000, 16)
    const float* w2 = (const float*)d_in[3];   // (40000, 16)
    const float* b2 = (const float*)d_in[4];   // (40000,)
    float* out = (float*)d_out;                // (128, 2, 20000) == (128, 40000)

    precompute_kernel<<<(CC * 4 + 255) / 256, 256>>>(w1, b1, w2, b2);  // 625 blocks

    dim3 grid((CC / 4 + 255) / 256, BB / RROWS);   // (40, 32) = 1280 blocks
    apply_kernel<<<grid, 256>>>(x, w1, b1, w2, out);
}

// round 6
// speedup vs baseline: 1.5598x; 1.1050x over previous
#include <cuda_runtime.h>

// ParallelBellowsLayers: per-channel 1->16->1 MLP with ReLU, C=40000, B=128, E=16.
// out[b,c] = relu( sum_e relu(x[b,c]*w1[c,e]+b1[c,e]) * w2[c,e] + b2[c] )
// Output (B,2,20000) is layout-identical to (B,C) row-major -> elementwise in x.
//
// When b1[c,:]==0 (true for this dataset):
//   sum_e relu(x*w1e)*w2e == x * (x>0 ? s_pos : s_neg)
// Precompute per channel s_pos/s_neg/b2 (SoA), then stream x -> out.
//
// R4 finding: DRAM traffic == sizeof(x) == 21 MB on EVERY graph replay and
// dur == 21MB / achieved-HBM-rate, independent of occupancy/MLP. The whole
// working set fits in the 126 MB L2, so pin it with an L2::evict_last cache
// policy (createpolicy + cache_hint form -- the inline .L2::evict_last
// modifier is only legal on .v8.b32 on sm_103, which is why R5 failed ptxas).

#define NGENES 20000
#define NTECH  2
#define CC     (NGENES * NTECH)   // 40000
#define BB     128
#define EE     16
#define RROWS  4                  // batch rows per thread in apply

// SoA per-channel params (NaN in g_sp[c] => exact-fallback channel)
__device__ float g_sp[CC];
__device__ float g_sn[CC];
__device__ float g_bf[CC];

// ---- L2 evict_last cache-policy memory ops ---------------------------------
__device__ __forceinline__ unsigned long long mk_policy()
{
    unsigned long long pol;
    asm volatile("createpolicy.fractional.L2::evict_last.b64 %0, 1.0;" : "=l"(pol));
    return pol;
}
__device__ __forceinline__ float4 ldg_el(const float* p, unsigned long long pol)
{
    float4 v;
    asm volatile("ld.global.nc.L2::cache_hint.v4.f32 {%0,%1,%2,%3}, [%4], %5;"
                 : "=f"(v.x), "=f"(v.y), "=f"(v.z), "=f"(v.w)
                 : "l"(p), "l"(pol));
    return v;
}
__device__ __forceinline__ float ldg_el1(const float* p, unsigned long long pol)
{
    float v;
    asm volatile("ld.global.nc.L2::cache_hint.f32 %0, [%1], %2;"
                 : "=f"(v) : "l"(p), "l"(pol));
    return v;
}
__device__ __forceinline__ void stg_el(float* p, float4 v, unsigned long long pol)
{
    asm volatile("st.global.L2::cache_hint.v4.f32 [%0], {%1,%2,%3,%4}, %5;"
                 :: "l"(p), "f"(v.x), "f"(v.y), "f"(v.z), "f"(v.w), "l"(pol)
                 : "memory");
}
// -----------------------------------------------------------------------------

// 4 threads per channel: each handles one float4 slice of E=16, shfl reduce.
__global__ void __launch_bounds__(256)
precompute_kernel(const float* __restrict__ w1,
                  const float* __restrict__ b1,
                  const float* __restrict__ w2,
                  const float* __restrict__ b2)
{
    int t = blockIdx.x * 256 + threadIdx.x;
    int c = t >> 2;
    int part = t & 3;
    if (c >= CC) return;

    unsigned long long pol = mk_policy();
    size_t off = ((size_t)c * 4 + part) * 4;   // float offset into (C,16) arrays
    float4 a = ldg_el(w1 + off, pol);
    float4 z = ldg_el(b1 + off, pol);
    float4 w = ldg_el(w2 + off, pol);

    bool ok = (z.x == 0.f) && (z.y == 0.f) && (z.z == 0.f) && (z.w == 0.f);

    float sp = 0.f, sn = 0.f, p;
    p = a.x * w.x; sp += (a.x > 0.f) ? p : 0.f; sn += (a.x < 0.f) ? p : 0.f;
    p = a.y * w.y; sp += (a.y > 0.f) ? p : 0.f; sn += (a.y < 0.f) ? p : 0.f;
    p = a.z * w.z; sp += (a.z > 0.f) ? p : 0.f; sn += (a.z < 0.f) ? p : 0.f;
    p = a.w * w.w; sp += (a.w > 0.f) ? p : 0.f; sn += (a.w < 0.f) ? p : 0.f;

    if (!ok) sp = __int_as_float(0x7fc00000);   // NaN survives the reduction

    sp += __shfl_xor_sync(0xffffffffu, sp, 1);
    sp += __shfl_xor_sync(0xffffffffu, sp, 2);
    sn += __shfl_xor_sync(0xffffffffu, sn, 1);
    sn += __shfl_xor_sync(0xffffffffu, sn, 2);

    if (part == 0) {
        if (!isfinite(sp) || !isfinite(sn)) sp = __int_as_float(0x7fc00000);
        g_sp[c] = sp;
        g_sn[c] = sn;
        g_bf[c] = ldg_el1(b2 + c, pol);
    }
}

// Exact per-element path for flagged channels (never taken on this dataset).
__device__ __noinline__ float bellows_exact(float xv, int c,
                                            const float* __restrict__ w1,
                                            const float* __restrict__ b1,
                                            const float* __restrict__ w2,
                                            float bias)
{
    float acc = 0.f;
    const float* w1r = w1 + (size_t)c * EE;
    const float* b1r = b1 + (size_t)c * EE;
    const float* w2r = w2 + (size_t)c * EE;
#pragma unroll 4
    for (int e = 0; e < EE; ++e) {
        float h = fmaxf(fmaf(xv, w1r[e], b1r[e]), 0.f);
        acc = fmaf(h, w2r[e], acc);
    }
    return fmaxf(acc + bias, 0.f);
}

__device__ __forceinline__ float bellows_fast(float xv, float sp, float sn, float bias)
{
    float s = (xv > 0.f) ? sp : sn;
    return fmaxf(fmaf(xv, s, bias), 0.f);
}

__global__ void __launch_bounds__(256)
apply_kernel(const float* __restrict__ x,
             const float* __restrict__ w1,
             const float* __restrict__ b1,
             const float* __restrict__ w2,
             float* __restrict__ out)
{
    int g = blockIdx.x * 256 + threadIdx.x;   // group of 4 channels
    if (g >= CC / 4) return;
    int c  = g * 4;
    int b0 = blockIdx.y * RROWS;

    unsigned long long pol = mk_policy();

    // 3 param loads (SoA, L2-pinned), amortized over RROWS rows.
    float4 sp = ldg_el(g_sp + c, pol);
    float4 sn = ldg_el(g_sn + c, pol);
    float4 bf = ldg_el(g_bf + c, pol);

    bool any_fb = (sp.x != sp.x) || (sp.y != sp.y) || (sp.z != sp.z) || (sp.w != sp.w);

    const float* xp = x + (size_t)b0 * CC + c;
    float*       op = out + (size_t)b0 * CC + c;

    if (!any_fb) {
        // Software pipeline: load row r+1 while computing/storing row r.
        float4 xa = ldg_el(xp, pol);
#pragma unroll
        for (int r = 0; r < RROWS; ++r) {
            float4 xb;
            if (r + 1 < RROWS)
                xb = ldg_el(xp + (size_t)(r + 1) * CC, pol);
            float4 o;
            o.x = bellows_fast(xa.x, sp.x, sn.x, bf.x);
            o.y = bellows_fast(xa.y, sp.y, sn.y, bf.y);
            o.z = bellows_fast(xa.z, sp.z, sn.z, bf.z);
            o.w = bellows_fast(xa.w, sp.w, sn.w, bf.w);
            stg_el(op + (size_t)r * CC, o, pol);
            xa = xb;
        }
    } else {
#pragma unroll
        for (int r = 0; r < RROWS; ++r) {
            float4 xv = ldg_el(xp + (size_t)r * CC, pol);
            float4 o;
            o.x = (sp.x != sp.x) ? bellows_exact(xv.x, c + 0, w1, b1, w2, bf.x)
                                 : bellows_fast(xv.x, sp.x, sn.x, bf.x);
            o.y = (sp.y != sp.y) ? bellows_exact(xv.y, c + 1, w1, b1, w2, bf.y)
                                 : bellows_fast(xv.y, sp.y, sn.y, bf.y);
            o.z = (sp.z != sp.z) ? bellows_exact(xv.z, c + 2, w1, b1, w2, bf.z)
                                 : bellows_fast(xv.z, sp.z, sn.z, bf.z);
            o.w = (sp.w != sp.w) ? bellows_exact(xv.w, c + 3, w1, b1, w2, bf.w)
                                 : bellows_fast(xv.w, sp.w, sn.w, bf.w);
            stg_el(op + (size_t)r * CC, o, pol);
        }
    }
}

extern "C" void kernel_launch(void* const* d_in, const int* in_sizes, int n_in,
                              void* d_out, int out_size)
{
    const float* x  = (const float*)d_in[0];   // (128, 40000)
    const float* w1 = (const float*)d_in[1];   // (40000, 16)
    const float* b1 = (const float*)d_in[2];   // (40000, 16)
    const float* w2 = (const float*)d_in[3];   // (40000, 16)
    const float* b2 = (const float*)d_in[4];   // (40000,)
    float* out = (float*)d_out;                // (128, 2, 20000) == (128, 40000)

    precompute_kernel<<<(CC * 4 + 255) / 256, 256>>>(w1, b1, w2, b2);  // 625 blocks

    dim3 grid((CC / 4 + 255) / 256, BB / RROWS);   // (40, 32) = 1280 blocks
    apply_kernel<<<grid, 256>>>(x, w1, b1, w2, out);
}